// round 12
// baseline (speedup 1.0000x reference)
#include <cuda_runtime.h>
#include <cstdint>
#include <cstddef>

#define TTOK   8192
#define DMODEL 1024
#define FDIM   4096
#define NEXP   8

#define BK       32
#define ASTRIDE  36          // words per A row (32 + pad) -> bank = 4r + c (bijective)
#define BSTRIDE  264         // words per B k-row (256 + pad) -> bank = 8k + n (bijective)
#define A_WORDS  (128 * ASTRIDE)   // 4608
#define B_WORDS  (BK * BSTRIDE)    // 8448
#define STAGES   3
#define DSMEM_BYTES ((STAGES * (A_WORDS + B_WORDS)) * 4)   // 156672

// ---------------- scratch (static device memory; no allocations) ------------
__device__ int   g_cnt[NEXP];
__device__ int   g_list[NEXP][TTOK];
__device__ float g_wslot[2 * TTOK];
__device__ float g_H[(size_t)2 * TTOK * FDIM];            // 256 MB
__device__ float g_O[(size_t)2 * TTOK * DMODEL];          // 64 MB

__global__ void k_init() {
    if (threadIdx.x < NEXP) g_cnt[threadIdx.x] = 0;
}

// ---------------- helpers ----------------------------------------------------
__device__ __forceinline__ uint32_t tf32u(float f) {
    uint32_t u;
    asm("cvt.rna.tf32.f32 %0, %1;" : "=r"(u) : "f"(f));
    return u;
}
__device__ __forceinline__ uint32_t smem_u32(const void* p) {
    uint32_t a;
    asm("{ .reg .u64 t; cvta.to.shared.u64 t, %1; cvt.u32.u64 %0, t; }"
        : "=r"(a) : "l"(p));
    return a;
}
__device__ __forceinline__ void cp16(uint32_t dst, const float* src, uint32_t srcsize) {
    asm volatile("cp.async.cg.shared.global [%0], [%1], 16, %2;"
                 :: "r"(dst), "l"(src), "r"(srcsize) : "memory");
}
#define CP_COMMIT() asm volatile("cp.async.commit_group;" ::: "memory")
#define CP_WAIT1()  asm volatile("cp.async.wait_group 1;" ::: "memory")

#define MMA_TF32(C, A, B0, B1)                                               \
    asm volatile(                                                            \
        "mma.sync.aligned.m16n8k8.row.col.f32.tf32.tf32.f32 "               \
        "{%0,%1,%2,%3},{%4,%5,%6,%7},{%8,%9},{%0,%1,%2,%3};"                \
        : "+f"((C)[0]), "+f"((C)[1]), "+f"((C)[2]), "+f"((C)[3])            \
        : "r"((A)[0]), "r"((A)[1]), "r"((A)[2]), "r"((A)[3]),               \
          "r"(B0), "r"(B1))

// ---------------- router ------------------------------------------------------
__global__ void __launch_bounds__(256) k_router(const float* __restrict__ x,
                                                const float* __restrict__ gw,
                                                float* logits) {
    __shared__ float sgw[NEXP * DMODEL];
    const int tid = threadIdx.x;
    for (int i = tid; i < NEXP * DMODEL / 4; i += 256)
        ((float4*)sgw)[i] = ((const float4*)gw)[i];
    __syncthreads();

    const int warp = tid >> 5, lane = tid & 31;
    const int t = blockIdx.x * 8 + warp;

    float acc[NEXP];
    #pragma unroll
    for (int e = 0; e < NEXP; e++) acc[e] = 0.f;

    const float4* xv = (const float4*)(x + (size_t)t * DMODEL);
    #pragma unroll
    for (int c = 0; c < DMODEL / 128; c++) {
        float4 xx = xv[c * 32 + lane];
        #pragma unroll
        for (int e = 0; e < NEXP; e++) {
            float4 g = ((const float4*)sgw)[e * (DMODEL / 4) + c * 32 + lane];
            acc[e] += xx.x * g.x + xx.y * g.y + xx.z * g.z + xx.w * g.w;
        }
    }
    #pragma unroll
    for (int off = 16; off > 0; off >>= 1) {
        #pragma unroll
        for (int e = 0; e < NEXP; e++)
            acc[e] += __shfl_xor_sync(0xffffffffu, acc[e], off);
    }

    if (lane == 0) {
        if (logits) {
            #pragma unroll
            for (int e = 0; e < NEXP; e++) logits[(size_t)t * NEXP + e] = acc[e];
        }
        int e0 = 0;
        #pragma unroll
        for (int e = 1; e < NEXP; e++) if (acc[e] > acc[e0]) e0 = e;
        int e1 = -1;
        #pragma unroll
        for (int e = 0; e < NEXP; e++) {
            if (e == e0) continue;
            if (e1 < 0 || acc[e] > acc[e1]) e1 = e;
        }
        float w0 = 1.f / (1.f + expf(acc[e1] - acc[e0]));
        float w1 = 1.f - w0;
        int s0 = atomicAdd(&g_cnt[e0], 1);
        g_list[e0][s0] = t * 2;
        int s1 = atomicAdd(&g_cnt[e1], 1);
        g_list[e1][s1] = t * 2 + 1;
        g_wslot[2 * t]     = w0;
        g_wslot[2 * t + 1] = w1;
    }
}

// ---------------- GEMM1: H = silu(x@W1) * (x@W3) -----------------------------
// CTA: 128 m x (128 W1-cols + 128 W3-cols), BK=32, 8 warps (2m x 4n),
// warp: 64 m x (32 W1 + 32 W3). 3-stage cp.async pipeline.
__global__ void __launch_bounds__(256) k_gemm1(const float* __restrict__ x,
                                               const float* __restrict__ W1,
                                               const float* __restrict__ W3) {
    const int e   = blockIdx.z;
    const int cnt = g_cnt[e];
    const int m0  = blockIdx.x * 128;
    if (m0 >= cnt) return;
    const int n0  = blockIdx.y * 128;

    extern __shared__ float ds[];
    __shared__ int sv[128];

    const int tid = threadIdx.x;
    if (tid < 128) sv[tid] = (m0 + tid < cnt) ? g_list[e][m0 + tid] : -1;
    __syncthreads();

    const uint32_t sbase = smem_u32(ds);

    // ---- staging descriptors ----
    // A: 4 chunks/thread: row r_t = (tid>>3)+32t, kc = (tid&7)*4
    const int akc = (tid & 7) * 4;
    const float* asrc[4];
    uint32_t adst[4], asz[4];
    #pragma unroll
    for (int t = 0; t < 4; t++) {
        const int r = (tid >> 3) + 32 * t;
        const int slot = sv[r];
        asrc[t] = x + (size_t)((slot < 0 ? 0 : slot) >> 1) * DMODEL + akc;
        asz[t]  = (slot >= 0) ? 16u : 0u;
        adst[t] = sbase + (uint32_t)(r * ASTRIDE + akc) * 4u;
    }
    // B: 8 chunks/thread: k = (tid>>6)+4t; j = tid&63 (j<32 -> W1, else W3)
    const int bj = tid & 63;
    const int bk0 = tid >> 6;
    const float* bsrc = ((bj < 32) ? W1 : W3) + (size_t)e * DMODEL * FDIM
                        + n0 + (bj & 31) * 4;
    const uint32_t bdst = sbase + (uint32_t)(STAGES * A_WORDS) * 4u
                        + (uint32_t)(bk0 * BSTRIDE + ((bj < 32) ? 0 : 128) + (bj & 31) * 4) * 4u;

    #define G1_STAGE(s, k0) do {                                              \
        const uint32_t _ao = (uint32_t)(s) * A_WORDS * 4u;                    \
        _Pragma("unroll")                                                     \
        for (int t = 0; t < 4; t++) cp16(adst[t] + _ao, asrc[t] + (k0), asz[t]); \
        const uint32_t _bo = (uint32_t)(s) * B_WORDS * 4u;                    \
        _Pragma("unroll")                                                     \
        for (int t = 0; t < 8; t++)                                           \
            cp16(bdst + _bo + (uint32_t)t * 4u * BSTRIDE * 4u,                \
                 bsrc + (size_t)((k0) + bk0 + 4 * t) * FDIM, 16u);            \
        CP_COMMIT();                                                          \
    } while (0)

    const int wid = tid >> 5, lane = tid & 31;
    const int wm = wid & 1, wn = wid >> 1;
    const int fr = lane >> 2, fc = lane & 3;

    float acc1[4][4][4], acc3[4][4][4];
    #pragma unroll
    for (int i = 0; i < 4; i++)
        #pragma unroll
        for (int n = 0; n < 4; n++)
            #pragma unroll
            for (int q = 0; q < 4; q++) { acc1[i][n][q] = 0.f; acc3[i][n][q] = 0.f; }

    const int NK = DMODEL / BK;   // 32
    G1_STAGE(0, 0);
    G1_STAGE(1, BK);

    for (int kt = 0; kt < NK; ++kt) {
        CP_WAIT1();
        __syncthreads();
        if (kt + 2 < NK) { G1_STAGE((kt + 2) % 3, (kt + 2) * BK); }
        else CP_COMMIT();

        const float* A_ = ds + (kt % 3) * A_WORDS;
        const float* B_ = ds + STAGES * A_WORDS + (kt % 3) * B_WORDS;

        #pragma unroll
        for (int s = 0; s < 4; s++) {
            const int kb = s * 8;
            uint32_t a[4][4];
            #pragma unroll
            for (int i = 0; i < 4; i++) {
                const int r = wm * 64 + i * 16 + fr;
                a[i][0] = tf32u(A_[r * ASTRIDE + kb + fc]);
                a[i][1] = tf32u(A_[(r + 8) * ASTRIDE + kb + fc]);
                a[i][2] = tf32u(A_[r * ASTRIDE + kb + fc + 4]);
                a[i][3] = tf32u(A_[(r + 8) * ASTRIDE + kb + fc + 4]);
            }
            #pragma unroll
            for (int nt = 0; nt < 4; nt++) {
                const int col = wn * 32 + nt * 8 + fr;
                uint32_t b10 = tf32u(B_[(kb + fc) * BSTRIDE + col]);
                uint32_t b11 = tf32u(B_[(kb + fc + 4) * BSTRIDE + col]);
                uint32_t b30 = tf32u(B_[(kb + fc) * BSTRIDE + 128 + col]);
                uint32_t b31 = tf32u(B_[(kb + fc + 4) * BSTRIDE + 128 + col]);
                #pragma unroll
                for (int i = 0; i < 4; i++) {
                    MMA_TF32(acc1[i][nt], a[i], b10, b11);
                    MMA_TF32(acc3[i][nt], a[i], b30, b31);
                }
            }
        }
        __syncthreads();
    }

    // epilogue: silu(acc1)*acc3 -> g_H
    #pragma unroll
    for (int i = 0; i < 4; i++) {
        const int r0 = wm * 64 + i * 16 + fr;
        const int v0 = sv[r0], v1 = sv[r0 + 8];
        #pragma unroll
        for (int nt = 0; nt < 4; nt++) {
            const int col = n0 + wn * 32 + nt * 8 + fc * 2;
            if (v0 >= 0) {
                float g0 = acc1[i][nt][0], g1 = acc1[i][nt][1];
                float2 h;
                h.x = g0 / (1.f + expf(-g0)) * acc3[i][nt][0];
                h.y = g1 / (1.f + expf(-g1)) * acc3[i][nt][1];
                *(float2*)(g_H + (size_t)v0 * FDIM + col) = h;
            }
            if (v1 >= 0) {
                float g2 = acc1[i][nt][2], g3 = acc1[i][nt][3];
                float2 h;
                h.x = g2 / (1.f + expf(-g2)) * acc3[i][nt][2];
                h.y = g3 / (1.f + expf(-g3)) * acc3[i][nt][3];
                *(float2*)(g_H + (size_t)v1 * FDIM + col) = h;
            }
        }
    }
    #undef G1_STAGE
}

// ---------------- GEMM2: O = H @ W2 -------------------------------------------
// CTA: 128 m x 256 n, BK=32, 8 warps (2m x 4n), warp 64x64.
__global__ void __launch_bounds__(256) k_gemm2(const float* __restrict__ W2) {
    const int e   = blockIdx.z;
    const int cnt = g_cnt[e];
    const int m0  = blockIdx.x * 128;
    if (m0 >= cnt) return;
    const int n0  = blockIdx.y * 256;

    extern __shared__ float ds[];
    __shared__ int sv[128];

    const int tid = threadIdx.x;
    if (tid < 128) sv[tid] = (m0 + tid < cnt) ? g_list[e][m0 + tid] : -1;
    __syncthreads();

    const uint32_t sbase = smem_u32(ds);

    const int akc = (tid & 7) * 4;
    const float* asrc[4];
    uint32_t adst[4], asz[4];
    #pragma unroll
    for (int t = 0; t < 4; t++) {
        const int r = (tid >> 3) + 32 * t;
        const int slot = sv[r];
        asrc[t] = g_H + (size_t)(slot < 0 ? 0 : slot) * FDIM + akc;
        asz[t]  = (slot >= 0) ? 16u : 0u;
        adst[t] = sbase + (uint32_t)(r * ASTRIDE + akc) * 4u;
    }
    const int bnc = (tid & 63) * 4;
    const int bk0 = tid >> 6;
    const float* bsrc = W2 + (size_t)e * FDIM * DMODEL + n0 + bnc;
    const uint32_t bdst = sbase + (uint32_t)(STAGES * A_WORDS) * 4u
                        + (uint32_t)(bk0 * BSTRIDE + bnc) * 4u;

    #define G2_STAGE(s, k0) do {                                              \
        const uint32_t _ao = (uint32_t)(s) * A_WORDS * 4u;                    \
        _Pragma("unroll")                                                     \
        for (int t = 0; t < 4; t++) cp16(adst[t] + _ao, asrc[t] + (k0), asz[t]); \
        const uint32_t _bo = (uint32_t)(s) * B_WORDS * 4u;                    \
        _Pragma("unroll")                                                     \
        for (int t = 0; t < 8; t++)                                           \
            cp16(bdst + _bo + (uint32_t)t * 4u * BSTRIDE * 4u,                \
                 bsrc + (size_t)((k0) + bk0 + 4 * t) * DMODEL, 16u);          \
        CP_COMMIT();                                                          \
    } while (0)

    const int wid = tid >> 5, lane = tid & 31;
    const int wm = wid & 1, wn = wid >> 1;
    const int fr = lane >> 2, fc = lane & 3;

    float acc[4][8][4];
    #pragma unroll
    for (int i = 0; i < 4; i++)
        #pragma unroll
        for (int n = 0; n < 8; n++)
            #pragma unroll
            for (int q = 0; q < 4; q++) acc[i][n][q] = 0.f;

    const int NK = FDIM / BK;   // 128
    G2_STAGE(0, 0);
    G2_STAGE(1, BK);

    for (int kt = 0; kt < NK; ++kt) {
        CP_WAIT1();
        __syncthreads();
        if (kt + 2 < NK) { G2_STAGE((kt + 2) % 3, (kt + 2) * BK); }
        else CP_COMMIT();

        const float* A_ = ds + (kt % 3) * A_WORDS;
        const float* B_ = ds + STAGES * A_WORDS + (kt % 3) * B_WORDS;

        #pragma unroll
        for (int s = 0; s < 4; s++) {
            const int kb = s * 8;
            uint32_t a[4][4];
            #pragma unroll
            for (int i = 0; i < 4; i++) {
                const int r = wm * 64 + i * 16 + fr;
                a[i][0] = tf32u(A_[r * ASTRIDE + kb + fc]);
                a[i][1] = tf32u(A_[(r + 8) * ASTRIDE + kb + fc]);
                a[i][2] = tf32u(A_[r * ASTRIDE + kb + fc + 4]);
                a[i][3] = tf32u(A_[(r + 8) * ASTRIDE + kb + fc + 4]);
            }
            #pragma unroll
            for (int nt = 0; nt < 8; nt++) {
                const int col = wn * 64 + nt * 8 + fr;
                uint32_t b0 = tf32u(B_[(kb + fc) * BSTRIDE + col]);
                uint32_t b1 = tf32u(B_[(kb + fc + 4) * BSTRIDE + col]);
                #pragma unroll
                for (int i = 0; i < 4; i++)
                    MMA_TF32(acc[i][nt], a[i], b0, b1);
            }
        }
        __syncthreads();
    }

    #pragma unroll
    for (int i = 0; i < 4; i++) {
        const int r0 = wm * 64 + i * 16 + fr;
        const int v0 = sv[r0], v1 = sv[r0 + 8];
        #pragma unroll
        for (int nt = 0; nt < 8; nt++) {
            const int col = n0 + wn * 64 + nt * 8 + fc * 2;
            if (v0 >= 0)
                *(float2*)(g_O + (size_t)v0 * DMODEL + col) =
                    make_float2(acc[i][nt][0], acc[i][nt][1]);
            if (v1 >= 0)
                *(float2*)(g_O + (size_t)v1 * DMODEL + col) =
                    make_float2(acc[i][nt][2], acc[i][nt][3]);
        }
    }
    #undef G2_STAGE
}

// ---------------- combine ------------------------------------------------------
__global__ void k_combine(float* __restrict__ out) {
    const int i  = blockIdx.x * blockDim.x + threadIdx.x;
    const int n4 = TTOK * DMODEL / 4;
    if (i >= n4) return;
    const int t = i / (DMODEL / 4);
    const int c = i % (DMODEL / 4);
    const float w0 = g_wslot[2 * t], w1 = g_wslot[2 * t + 1];
    const float4 o0 = ((const float4*)g_O)[(size_t)(2 * t)     * (DMODEL / 4) + c];
    const float4 o1 = ((const float4*)g_O)[(size_t)(2 * t + 1) * (DMODEL / 4) + c];
    float4 r;
    r.x = w0 * o0.x + w1 * o1.x;
    r.y = w0 * o0.y + w1 * o1.y;
    r.z = w0 * o0.z + w1 * o1.z;
    r.w = w0 * o0.w + w1 * o1.w;
    ((float4*)out)[i] = r;
}

// ---------------- launch --------------------------------------------------------
extern "C" void kernel_launch(void* const* d_in, const int* in_sizes, int n_in,
                              void* d_out, int out_size) {
    const float* x  = (const float*)d_in[0];
    const float* gw = (const float*)d_in[1];
    const float* W1 = (const float*)d_in[2];
    const float* W3 = (const float*)d_in[3];
    const float* W2 = (const float*)d_in[4];
    float* out = (float*)d_out;

    float* logits = ((size_t)out_size >= (size_t)TTOK * DMODEL + (size_t)TTOK * NEXP)
                        ? out + (size_t)TTOK * DMODEL
                        : nullptr;

    static int smem_set = 0;
    if (!smem_set) {
        cudaFuncSetAttribute(k_gemm1, cudaFuncAttributeMaxDynamicSharedMemorySize, DSMEM_BYTES);
        cudaFuncSetAttribute(k_gemm2, cudaFuncAttributeMaxDynamicSharedMemorySize, DSMEM_BYTES);
        smem_set = 1;
    }

    k_init<<<1, 32>>>();
    k_router<<<TTOK / 8, 256>>>(x, gw, logits);
    // m-blocks fastest: co-resident CTAs share the same B panel through L2.
    k_gemm1<<<dim3(TTOK / 128, FDIM / 128, NEXP), 256, DSMEM_BYTES>>>(x, W1, W3);
    k_gemm2<<<dim3(TTOK / 128, DMODEL / 256, NEXP), 256, DSMEM_BYTES>>>(W2);
    k_combine<<<(TTOK * DMODEL / 4 + 255) / 256, 256>>>(out);
}

// round 13
// speedup vs baseline: 1.0009x; 1.0009x over previous
#include <cuda_runtime.h>
#include <cstdint>
#include <cstddef>

#define TTOK   8192
#define DMODEL 1024
#define FDIM   4096
#define NEXP   8

#define BK       32
#define ASTRIDE  36          // words per A row (32 + pad) -> bank = 4r + c (bijective)
#define BSTRIDE  264         // words per B k-row (256 + pad) -> bank = 8k + n (bijective)
#define A_WORDS  (128 * ASTRIDE)   // 4608
#define B_WORDS  (BK * BSTRIDE)    // 8448
#define STAGES   3
#define DSMEM_BYTES ((STAGES * (A_WORDS + B_WORDS)) * 4)   // 156672

// ---------------- scratch (static device memory; no allocations) ------------
__device__ int   g_cnt[NEXP];
__device__ int   g_list[NEXP][TTOK];
__device__ float g_wslot[2 * TTOK];
__device__ float g_H[(size_t)2 * TTOK * FDIM];            // 256 MB
__device__ float g_O[(size_t)2 * TTOK * DMODEL];          // 64 MB

__global__ void k_init() {
    if (threadIdx.x < NEXP) g_cnt[threadIdx.x] = 0;
}

// ---------------- helpers ----------------------------------------------------
__device__ __forceinline__ uint32_t tf32u(float f) {
    uint32_t u;
    asm("cvt.rna.tf32.f32 %0, %1;" : "=r"(u) : "f"(f));
    return u;
}
__device__ __forceinline__ uint32_t smem_u32(const void* p) {
    uint32_t a;
    asm("{ .reg .u64 t; cvta.to.shared.u64 t, %1; cvt.u32.u64 %0, t; }"
        : "=r"(a) : "l"(p));
    return a;
}
__device__ __forceinline__ void cp16(uint32_t dst, const float* src, uint32_t srcsize) {
    asm volatile("cp.async.cg.shared.global [%0], [%1], 16, %2;"
                 :: "r"(dst), "l"(src), "r"(srcsize) : "memory");
}
#define CP_COMMIT() asm volatile("cp.async.commit_group;" ::: "memory")
#define CP_WAIT1()  asm volatile("cp.async.wait_group 1;" ::: "memory")

#define MMA_TF32(C, A, B0, B1)                                               \
    asm volatile(                                                            \
        "mma.sync.aligned.m16n8k8.row.col.f32.tf32.tf32.f32 "               \
        "{%0,%1,%2,%3},{%4,%5,%6,%7},{%8,%9},{%0,%1,%2,%3};"                \
        : "+f"((C)[0]), "+f"((C)[1]), "+f"((C)[2]), "+f"((C)[3])            \
        : "r"((A)[0]), "r"((A)[1]), "r"((A)[2]), "r"((A)[3]),               \
          "r"(B0), "r"(B1))

// ---------------- router ------------------------------------------------------
__global__ void __launch_bounds__(256) k_router(const float* __restrict__ x,
                                                const float* __restrict__ gw,
                                                float* logits) {
    __shared__ float sgw[NEXP * DMODEL];
    const int tid = threadIdx.x;
    for (int i = tid; i < NEXP * DMODEL / 4; i += 256)
        ((float4*)sgw)[i] = ((const float4*)gw)[i];
    __syncthreads();

    const int warp = tid >> 5, lane = tid & 31;
    const int t = blockIdx.x * 8 + warp;

    float acc[NEXP];
    #pragma unroll
    for (int e = 0; e < NEXP; e++) acc[e] = 0.f;

    const float4* xv = (const float4*)(x + (size_t)t * DMODEL);
    #pragma unroll
    for (int c = 0; c < DMODEL / 128; c++) {
        float4 xx = xv[c * 32 + lane];
        #pragma unroll
        for (int e = 0; e < NEXP; e++) {
            float4 g = ((const float4*)sgw)[e * (DMODEL / 4) + c * 32 + lane];
            acc[e] += xx.x * g.x + xx.y * g.y + xx.z * g.z + xx.w * g.w;
        }
    }
    #pragma unroll
    for (int off = 16; off > 0; off >>= 1) {
        #pragma unroll
        for (int e = 0; e < NEXP; e++)
            acc[e] += __shfl_xor_sync(0xffffffffu, acc[e], off);
    }

    if (lane == 0) {
        if (logits) {
            #pragma unroll
            for (int e = 0; e < NEXP; e++) logits[(size_t)t * NEXP + e] = acc[e];
        }
        int e0 = 0;
        #pragma unroll
        for (int e = 1; e < NEXP; e++) if (acc[e] > acc[e0]) e0 = e;
        int e1 = -1;
        #pragma unroll
        for (int e = 0; e < NEXP; e++) {
            if (e == e0) continue;
            if (e1 < 0 || acc[e] > acc[e1]) e1 = e;
        }
        float w0 = 1.f / (1.f + expf(acc[e1] - acc[e0]));
        float w1 = 1.f - w0;
        int s0 = atomicAdd(&g_cnt[e0], 1);
        g_list[e0][s0] = t * 2;
        int s1 = atomicAdd(&g_cnt[e1], 1);
        g_list[e1][s1] = t * 2 + 1;
        g_wslot[2 * t]     = w0;
        g_wslot[2 * t + 1] = w1;
    }
}

// ---------------- GEMM1: H = silu(x@W1) * (x@W3) -----------------------------
// CTA: 128 m x (128 W1-cols + 128 W3-cols), BK=32, 8 warps (2m x 4n),
// warp: 64 m x (32 W1 + 32 W3). 3-stage cp.async pipeline.
__global__ void __launch_bounds__(256) k_gemm1(const float* __restrict__ x,
                                               const float* __restrict__ W1,
                                               const float* __restrict__ W3) {
    const int e   = blockIdx.z;
    const int cnt = g_cnt[e];
    const int m0  = blockIdx.x * 128;
    if (m0 >= cnt) return;
    const int n0  = blockIdx.y * 128;

    extern __shared__ float ds[];
    __shared__ int sv[128];

    const int tid = threadIdx.x;
    if (tid < 128) sv[tid] = (m0 + tid < cnt) ? g_list[e][m0 + tid] : -1;
    __syncthreads();

    const uint32_t sbase = smem_u32(ds);

    // ---- staging descriptors ----
    // A: 4 chunks/thread: row r_t = (tid>>3)+32t, kc = (tid&7)*4
    const int akc = (tid & 7) * 4;
    const float* asrc[4];
    uint32_t adst[4], asz[4];
    #pragma unroll
    for (int t = 0; t < 4; t++) {
        const int r = (tid >> 3) + 32 * t;
        const int slot = sv[r];
        asrc[t] = x + (size_t)((slot < 0 ? 0 : slot) >> 1) * DMODEL + akc;
        asz[t]  = (slot >= 0) ? 16u : 0u;
        adst[t] = sbase + (uint32_t)(r * ASTRIDE + akc) * 4u;
    }
    // B: 8 chunks/thread: k = (tid>>6)+4t; j = tid&63 (j<32 -> W1, else W3)
    const int bj = tid & 63;
    const int bk0 = tid >> 6;
    const float* bsrc = ((bj < 32) ? W1 : W3) + (size_t)e * DMODEL * FDIM
                        + n0 + (bj & 31) * 4;
    const uint32_t bdst = sbase + (uint32_t)(STAGES * A_WORDS) * 4u
                        + (uint32_t)(bk0 * BSTRIDE + ((bj < 32) ? 0 : 128) + (bj & 31) * 4) * 4u;

    #define G1_STAGE(s, k0) do {                                              \
        const uint32_t _ao = (uint32_t)(s) * A_WORDS * 4u;                    \
        _Pragma("unroll")                                                     \
        for (int t = 0; t < 4; t++) cp16(adst[t] + _ao, asrc[t] + (k0), asz[t]); \
        const uint32_t _bo = (uint32_t)(s) * B_WORDS * 4u;                    \
        _Pragma("unroll")                                                     \
        for (int t = 0; t < 8; t++)                                           \
            cp16(bdst + _bo + (uint32_t)t * 4u * BSTRIDE * 4u,                \
                 bsrc + (size_t)((k0) + bk0 + 4 * t) * FDIM, 16u);            \
        CP_COMMIT();                                                          \
    } while (0)

    const int wid = tid >> 5, lane = tid & 31;
    const int wm = wid & 1, wn = wid >> 1;
    const int fr = lane >> 2, fc = lane & 3;

    float acc1[4][4][4], acc3[4][4][4];
    #pragma unroll
    for (int i = 0; i < 4; i++)
        #pragma unroll
        for (int n = 0; n < 4; n++)
            #pragma unroll
            for (int q = 0; q < 4; q++) { acc1[i][n][q] = 0.f; acc3[i][n][q] = 0.f; }

    const int NK = DMODEL / BK;   // 32
    G1_STAGE(0, 0);
    G1_STAGE(1, BK);

    for (int kt = 0; kt < NK; ++kt) {
        CP_WAIT1();
        __syncthreads();
        if (kt + 2 < NK) { G1_STAGE((kt + 2) % 3, (kt + 2) * BK); }
        else CP_COMMIT();

        const float* A_ = ds + (kt % 3) * A_WORDS;
        const float* B_ = ds + STAGES * A_WORDS + (kt % 3) * B_WORDS;

        #pragma unroll
        for (int s = 0; s < 4; s++) {
            const int kb = s * 8;
            uint32_t a[4][4];
            #pragma unroll
            for (int i = 0; i < 4; i++) {
                const int r = wm * 64 + i * 16 + fr;
                a[i][0] = tf32u(A_[r * ASTRIDE + kb + fc]);
                a[i][1] = tf32u(A_[(r + 8) * ASTRIDE + kb + fc]);
                a[i][2] = tf32u(A_[r * ASTRIDE + kb + fc + 4]);
                a[i][3] = tf32u(A_[(r + 8) * ASTRIDE + kb + fc + 4]);
            }
            #pragma unroll
            for (int nt = 0; nt < 4; nt++) {
                const int col = wn * 32 + nt * 8 + fr;
                uint32_t b10 = tf32u(B_[(kb + fc) * BSTRIDE + col]);
                uint32_t b11 = tf32u(B_[(kb + fc + 4) * BSTRIDE + col]);
                uint32_t b30 = tf32u(B_[(kb + fc) * BSTRIDE + 128 + col]);
                uint32_t b31 = tf32u(B_[(kb + fc + 4) * BSTRIDE + 128 + col]);
                #pragma unroll
                for (int i = 0; i < 4; i++) {
                    MMA_TF32(acc1[i][nt], a[i], b10, b11);
                    MMA_TF32(acc3[i][nt], a[i], b30, b31);
                }
            }
        }
        __syncthreads();
    }

    // epilogue: silu(acc1)*acc3 -> g_H
    #pragma unroll
    for (int i = 0; i < 4; i++) {
        const int r0 = wm * 64 + i * 16 + fr;
        const int v0 = sv[r0], v1 = sv[r0 + 8];
        #pragma unroll
        for (int nt = 0; nt < 4; nt++) {
            const int col = n0 + wn * 32 + nt * 8 + fc * 2;
            if (v0 >= 0) {
                float g0 = acc1[i][nt][0], g1 = acc1[i][nt][1];
                float2 h;
                h.x = g0 / (1.f + expf(-g0)) * acc3[i][nt][0];
                h.y = g1 / (1.f + expf(-g1)) * acc3[i][nt][1];
                *(float2*)(g_H + (size_t)v0 * FDIM + col) = h;
            }
            if (v1 >= 0) {
                float g2 = acc1[i][nt][2], g3 = acc1[i][nt][3];
                float2 h;
                h.x = g2 / (1.f + expf(-g2)) * acc3[i][nt][2];
                h.y = g3 / (1.f + expf(-g3)) * acc3[i][nt][3];
                *(float2*)(g_H + (size_t)v1 * FDIM + col) = h;
            }
        }
    }
    #undef G1_STAGE
}

// ---------------- GEMM2: O = H @ W2 -------------------------------------------
// CTA: 128 m x 256 n, BK=32, 8 warps (2m x 4n), warp 64x64.
__global__ void __launch_bounds__(256) k_gemm2(const float* __restrict__ W2) {
    const int e   = blockIdx.z;
    const int cnt = g_cnt[e];
    const int m0  = blockIdx.x * 128;
    if (m0 >= cnt) return;
    const int n0  = blockIdx.y * 256;

    extern __shared__ float ds[];
    __shared__ int sv[128];

    const int tid = threadIdx.x;
    if (tid < 128) sv[tid] = (m0 + tid < cnt) ? g_list[e][m0 + tid] : -1;
    __syncthreads();

    const uint32_t sbase = smem_u32(ds);

    const int akc = (tid & 7) * 4;
    const float* asrc[4];
    uint32_t adst[4], asz[4];
    #pragma unroll
    for (int t = 0; t < 4; t++) {
        const int r = (tid >> 3) + 32 * t;
        const int slot = sv[r];
        asrc[t] = g_H + (size_t)(slot < 0 ? 0 : slot) * FDIM + akc;
        asz[t]  = (slot >= 0) ? 16u : 0u;
        adst[t] = sbase + (uint32_t)(r * ASTRIDE + akc) * 4u;
    }
    const int bnc = (tid & 63) * 4;
    const int bk0 = tid >> 6;
    const float* bsrc = W2 + (size_t)e * FDIM * DMODEL + n0 + bnc;
    const uint32_t bdst = sbase + (uint32_t)(STAGES * A_WORDS) * 4u
                        + (uint32_t)(bk0 * BSTRIDE + bnc) * 4u;

    #define G2_STAGE(s, k0) do {                                              \
        const uint32_t _ao = (uint32_t)(s) * A_WORDS * 4u;                    \
        _Pragma("unroll")                                                     \
        for (int t = 0; t < 4; t++) cp16(adst[t] + _ao, asrc[t] + (k0), asz[t]); \
        const uint32_t _bo = (uint32_t)(s) * B_WORDS * 4u;                    \
        _Pragma("unroll")                                                     \
        for (int t = 0; t < 8; t++)                                           \
            cp16(bdst + _bo + (uint32_t)t * 4u * BSTRIDE * 4u,                \
                 bsrc + (size_t)((k0) + bk0 + 4 * t) * DMODEL, 16u);          \
        CP_COMMIT();                                                          \
    } while (0)

    const int wid = tid >> 5, lane = tid & 31;
    const int wm = wid & 1, wn = wid >> 1;
    const int fr = lane >> 2, fc = lane & 3;

    float acc[4][8][4];
    #pragma unroll
    for (int i = 0; i < 4; i++)
        #pragma unroll
        for (int n = 0; n < 8; n++)
            #pragma unroll
            for (int q = 0; q < 4; q++) acc[i][n][q] = 0.f;

    const int NK = FDIM / BK;   // 128
    G2_STAGE(0, 0);
    G2_STAGE(1, BK);

    for (int kt = 0; kt < NK; ++kt) {
        CP_WAIT1();
        __syncthreads();
        if (kt + 2 < NK) { G2_STAGE((kt + 2) % 3, (kt + 2) * BK); }
        else CP_COMMIT();

        const float* A_ = ds + (kt % 3) * A_WORDS;
        const float* B_ = ds + STAGES * A_WORDS + (kt % 3) * B_WORDS;

        #pragma unroll
        for (int s = 0; s < 4; s++) {
            const int kb = s * 8;
            uint32_t a[4][4];
            #pragma unroll
            for (int i = 0; i < 4; i++) {
                const int r = wm * 64 + i * 16 + fr;
                a[i][0] = tf32u(A_[r * ASTRIDE + kb + fc]);
                a[i][1] = tf32u(A_[(r + 8) * ASTRIDE + kb + fc]);
                a[i][2] = tf32u(A_[r * ASTRIDE + kb + fc + 4]);
                a[i][3] = tf32u(A_[(r + 8) * ASTRIDE + kb + fc + 4]);
            }
            #pragma unroll
            for (int nt = 0; nt < 8; nt++) {
                const int col = wn * 64 + nt * 8 + fr;
                uint32_t b0 = tf32u(B_[(kb + fc) * BSTRIDE + col]);
                uint32_t b1 = tf32u(B_[(kb + fc + 4) * BSTRIDE + col]);
                #pragma unroll
                for (int i = 0; i < 4; i++)
                    MMA_TF32(acc[i][nt], a[i], b0, b1);
            }
        }
        __syncthreads();
    }

    #pragma unroll
    for (int i = 0; i < 4; i++) {
        const int r0 = wm * 64 + i * 16 + fr;
        const int v0 = sv[r0], v1 = sv[r0 + 8];
        #pragma unroll
        for (int nt = 0; nt < 8; nt++) {
            const int col = n0 + wn * 64 + nt * 8 + fc * 2;
            if (v0 >= 0)
                *(float2*)(g_O + (size_t)v0 * DMODEL + col) =
                    make_float2(acc[i][nt][0], acc[i][nt][1]);
            if (v1 >= 0)
                *(float2*)(g_O + (size_t)v1 * DMODEL + col) =
                    make_float2(acc[i][nt][2], acc[i][nt][3]);
        }
    }
    #undef G2_STAGE
}

// ---------------- combine ------------------------------------------------------
__global__ void k_combine(float* __restrict__ out) {
    const int i  = blockIdx.x * blockDim.x + threadIdx.x;
    const int n4 = TTOK * DMODEL / 4;
    if (i >= n4) return;
    const int t = i / (DMODEL / 4);
    const int c = i % (DMODEL / 4);
    const float w0 = g_wslot[2 * t], w1 = g_wslot[2 * t + 1];
    const float4 o0 = ((const float4*)g_O)[(size_t)(2 * t)     * (DMODEL / 4) + c];
    const float4 o1 = ((const float4*)g_O)[(size_t)(2 * t + 1) * (DMODEL / 4) + c];
    float4 r;
    r.x = w0 * o0.x + w1 * o1.x;
    r.y = w0 * o0.y + w1 * o1.y;
    r.z = w0 * o0.z + w1 * o1.z;
    r.w = w0 * o0.w + w1 * o1.w;
    ((float4*)out)[i] = r;
}

// ---------------- launch --------------------------------------------------------
extern "C" void kernel_launch(void* const* d_in, const int* in_sizes, int n_in,
                              void* d_out, int out_size) {
    const float* x  = (const float*)d_in[0];
    const float* gw = (const float*)d_in[1];
    const float* W1 = (const float*)d_in[2];
    const float* W3 = (const float*)d_in[3];
    const float* W2 = (const float*)d_in[4];
    float* out = (float*)d_out;

    float* logits = ((size_t)out_size >= (size_t)TTOK * DMODEL + (size_t)TTOK * NEXP)
                        ? out + (size_t)TTOK * DMODEL
                        : nullptr;

    static int smem_set = 0;
    if (!smem_set) {
        cudaFuncSetAttribute(k_gemm1, cudaFuncAttributeMaxDynamicSharedMemorySize, DSMEM_BYTES);
        cudaFuncSetAttribute(k_gemm2, cudaFuncAttributeMaxDynamicSharedMemorySize, DSMEM_BYTES);
        smem_set = 1;
    }

    k_init<<<1, 32>>>();
    k_router<<<TTOK / 8, 256>>>(x, gw, logits);
    // m-blocks fastest: co-resident CTAs share the same B panel through L2.
    k_gemm1<<<dim3(TTOK / 128, FDIM / 128, NEXP), 256, DSMEM_BYTES>>>(x, W1, W3);
    k_gemm2<<<dim3(TTOK / 128, DMODEL / 256, NEXP), 256, DSMEM_BYTES>>>(W2);
    k_combine<<<(TTOK * DMODEL / 4 + 255) / 256, 256>>>(out);
}